// round 14
// baseline (speedup 1.0000x reference)
#include <cuda_runtime.h>
#include <cuda_bf16.h>
#include <cstdint>

#define FULL_MASK 0xFFFFFFFFu

constexpr int E_EDGES = 65536;
constexpr int F_DIM   = 128;
constexpr int D_DEG   = 32;
constexpr int THREADS = 256;
constexpr int BLOCKS  = 1184;                     // 148 SMs x 8 blocks = 2048 thr/SM
constexpr int N_WARPS = BLOCKS * (THREADS / 32);  // 9472 warps, ~7 edges each
constexpr int WPB     = THREADS / 32;

__device__ __forceinline__ void cpa16(uint32_t smem_dst, const void* gsrc) {
    asm volatile("cp.async.cg.shared.global [%0], [%1], 16;" :: "r"(smem_dst), "l"(gsrc));
}
#define CP_COMMIT()   asm volatile("cp.async.commit_group;" ::: "memory")
#define CP_WAIT1()    asm volatile("cp.async.wait_group 1;" ::: "memory")
#define CP_WAIT_ALL() asm volatile("cp.async.wait_group 0;" ::: "memory")

// R13's per-warp double-buffered cp.async staging, trimmed to 32 regs so it
// runs at FULL occupancy (8 blocks/SM): high per-warp MLP (zero-register
// in-flight rows) AND 64 resident warps/SM simultaneously.
__global__ void __launch_bounds__(THREADS, 8)
ncn_kernel(const float* __restrict__ x,
           const int*   __restrict__ nbr,
           const int*   __restrict__ tar_ei,
           const float* __restrict__ W,
           const float* __restrict__ b,
           float*       __restrict__ out)
{
    // [warp][stage][row(i,j)] : x rows 512B each, nbr rows 128B each
    __shared__ __align__(16) float xbuf[WPB][2][2][F_DIM];   // 16 KB
    __shared__ __align__(16) int   nbuf[WPB][2][2][D_DEG];   //  2 KB

    const int lane = threadIdx.x & 31;
    const int wloc = threadIdx.x >> 5;

    const uint32_t xb = (uint32_t)__cvta_generic_to_shared(&xbuf[wloc][0][0][0]);
    const uint32_t nb = (uint32_t)__cvta_generic_to_shared(&nbuf[wloc][0][0][0]);

    // Per-lane weight slices (reused every iteration -> L1 path).
    const float4 w0 = __ldg(&reinterpret_cast<const float4*>(W)[lane]);
    const float4 w1 = __ldg(&reinterpret_cast<const float4*>(W + F_DIM)[lane]);
    const float  bv = __ldg(b);

    const float4* xv = reinterpret_cast<const float4*>(x);

    // ---- prologue: stage first edge into buffer 0 ----
    int e = (blockIdx.x * blockDim.x + threadIdx.x) >> 5;   // warp id < E
    {
        const int i0 = __ldg(tar_ei + e);
        const int j0 = __ldg(tar_ei + E_EDGES + e);
        cpa16(xb + lane * 16,       x + (size_t)i0 * F_DIM + lane * 4);
        cpa16(xb + 512 + lane * 16, x + (size_t)j0 * F_DIM + lane * 4);
        if (lane < 16) {
            const int r = (lane < 8) ? i0 : j0;   // lanes 0-7: ni row, 8-15: nj row
            cpa16(nb + (lane >> 3) * 128 + (lane & 7) * 16,
                  nbr + (size_t)r * D_DEG + (lane & 7) * 4);
        }
        CP_COMMIT();
    }

    int s = 0;
    while (true) {
        // ---- stage NEXT edge into buffer s^1 (idx loaded here; serialization
        //      hidden because staging runs one edge ahead of compute) ----
        const int e1  = e + N_WARPS;
        const int ec1 = min(e1, E_EDGES - 1);
        {
            const int i1 = __ldg(tar_ei + ec1);
            const int j1 = __ldg(tar_ei + E_EDGES + ec1);
            const uint32_t t = (uint32_t)(s ^ 1);
            cpa16(xb + t * 1024 + lane * 16,       x + (size_t)i1 * F_DIM + lane * 4);
            cpa16(xb + t * 1024 + 512 + lane * 16, x + (size_t)j1 * F_DIM + lane * 4);
            if (lane < 16) {
                const int r = (lane < 8) ? i1 : j1;
                cpa16(nb + t * 256 + (lane >> 3) * 128 + (lane & 7) * 16,
                      nbr + (size_t)r * D_DEG + (lane & 7) * 4);
            }
            CP_COMMIT();
        }

        // ---- current stage ready (all groups except the just-issued one) ----
        CP_WAIT1();
        __syncwarp();

        const float4 a = reinterpret_cast<const float4*>(xbuf[wloc][s][0])[lane];
        const float4 c = reinterpret_cast<const float4*>(xbuf[wloc][s][1])[lane];
        const int ni_l = nbuf[wloc][s][0][lane];
        const int nj_l = nbuf[wloc][s][1][lane];

        float acc = a.x*c.x*w0.x + a.y*c.y*w0.y + a.z*c.z*w0.z + a.w*c.w*w0.w;

        // lower_bound of ni_l in sorted distributed nj (clip + equality,
        // matching jnp.searchsorted semantics in the reference).
        int lo = 0, hi = D_DEG - 1;
        #pragma unroll
        for (int st = 0; st < 5; ++st) {
            const int mid = (lo + hi) >> 1;
            const int v   = __shfl_sync(FULL_MASK, nj_l, mid);
            if (v < ni_l) lo = mid + 1; else hi = mid;
        }
        const bool hit = (__shfl_sync(FULL_MASK, nj_l, lo) == ni_l);

        // Rare common-neighbor contributions (warp-uniform mask).
        unsigned hm = __ballot_sync(FULL_MASK, hit);
        while (hm) {
            const int h = __ffs(hm) - 1; hm &= hm - 1u;
            const int cn = __shfl_sync(FULL_MASK, ni_l, h);
            const float4 xc = __ldg(&xv[(size_t)cn * (F_DIM/4) + lane]);
            acc += xc.x*w1.x + xc.y*w1.y + xc.z*w1.z + xc.w*w1.w;
        }

        // Warp reduction (butterfly).
        #pragma unroll
        for (int off = 16; off >= 1; off >>= 1)
            acc += __shfl_down_sync(FULL_MASK, acc, off);

        if (lane == 0) out[e] = acc + bv;

        __syncwarp();           // stage s fully consumed before next refill

        if (e1 >= E_EDGES) break;
        e = e1;
        s ^= 1;
    }

    CP_WAIT_ALL();              // drain outstanding async copies before exit
}

extern "C" void kernel_launch(void* const* d_in, const int* in_sizes, int n_in,
                              void* d_out, int out_size)
{
    const float* x      = (const float*)d_in[0];
    const int*   nbr    = (const int*)  d_in[1];
    const int*   tar_ei = (const int*)  d_in[2];
    const float* W      = (const float*)d_in[3];
    const float* b      = (const float*)d_in[4];
    float*       out    = (float*)d_out;

    ncn_kernel<<<BLOCKS, THREADS>>>(x, nbr, tar_ei, W, b, out);
}

// round 15
// speedup vs baseline: 1.1425x; 1.1425x over previous
#include <cuda_runtime.h>
#include <cuda_bf16.h>
#include <cstdint>

#define FULL_MASK 0xFFFFFFFFu

constexpr int E_EDGES = 65536;
constexpr int F_DIM   = 128;
constexpr int D_DEG   = 32;

// One warp per edge, grid-stride (R1 structure — session best at 14.37us).
//   lane l owns feature channels [4l, 4l+4) as a float4, and neighbor slot l.
// Only change vs R1: nbr loads issued before x-row loads, since the
// nbr -> binary-search -> ballot chain is the longest dependent path.
// out[e] = sum_f xi[f]*xj[f]*W[f] + sum_{d: ni[d] in nj} dot(x[ni[d]], W[F:2F]) + b
__global__ void __launch_bounds__(256, 8)
ncn_kernel(const float* __restrict__ x,
           const int*   __restrict__ nbr,
           const int*   __restrict__ tar_ei,
           const float* __restrict__ W,
           const float* __restrict__ b,
           float*       __restrict__ out)
{
    const int lane    = threadIdx.x & 31;
    const int warp_id = (blockIdx.x * blockDim.x + threadIdx.x) >> 5;
    const int n_warps = (gridDim.x * blockDim.x) >> 5;

    // Per-lane weight slices (W is [256,1] contiguous): W0 = W[0:128], W1 = W[128:256]
    const float4 w0 = __ldg(&reinterpret_cast<const float4*>(W)[lane]);
    const float4 w1 = __ldg(&reinterpret_cast<const float4*>(W + F_DIM)[lane]);
    const float  bv = __ldg(b);

    const float4* xv = reinterpret_cast<const float4*>(x);

    for (int e = warp_id; e < E_EDGES; e += n_warps) {
        const int i = __ldg(tar_ei + e);            // tar_ei[0][e]
        const int j = __ldg(tar_ei + E_EDGES + e);  // tar_ei[1][e]

        // Neighbor lists first (head of the longest dependent chain),
        // one entry per lane (128B coalesced per row).
        const int ni_l = __ldg(nbr + (size_t)i * D_DEG + lane);
        const int nj_l = __ldg(nbr + (size_t)j * D_DEG + lane);

        // Endpoint feature rows: 512B per row, fully coalesced across the warp.
        const float4 a = __ldg(&xv[(size_t)i * (F_DIM/4) + lane]);
        const float4 c = __ldg(&xv[(size_t)j * (F_DIM/4) + lane]);

        // (xi * xj) . W0, per-lane partial
        float acc = a.x*c.x*w0.x + a.y*c.y*w0.y + a.z*c.z*w0.z + a.w*c.w*w0.w;

        // lower_bound of ni_l in the sorted distributed nj (clip to D-1 +
        // equality test, matching jnp.searchsorted semantics in the reference).
        int lo = 0, hi = D_DEG - 1;
        #pragma unroll
        for (int s = 0; s < 5; ++s) {
            const int mid = (lo + hi) >> 1;
            const int v   = __shfl_sync(FULL_MASK, nj_l, mid);
            if (v < ni_l) lo = mid + 1; else hi = mid;
        }
        const bool hit = (__shfl_sync(FULL_MASK, nj_l, lo) == ni_l);

        // Rare common-neighbor contributions (warp-uniform mask keeps convergence).
        unsigned hm = __ballot_sync(FULL_MASK, hit);
        while (hm) {
            const int h = __ffs(hm) - 1; hm &= hm - 1u;
            const int cn = __shfl_sync(FULL_MASK, ni_l, h);
            const float4 xc = __ldg(&xv[(size_t)cn * (F_DIM/4) + lane]);
            acc += xc.x*w1.x + xc.y*w1.y + xc.z*w1.z + xc.w*w1.w;
        }

        // Warp reduction (butterfly).
        #pragma unroll
        for (int off = 16; off >= 1; off >>= 1)
            acc += __shfl_down_sync(FULL_MASK, acc, off);

        if (lane == 0) out[e] = acc + bv;
    }
}

extern "C" void kernel_launch(void* const* d_in, const int* in_sizes, int n_in,
                              void* d_out, int out_size)
{
    const float* x      = (const float*)d_in[0];
    const int*   nbr    = (const int*)  d_in[1];
    const int*   tar_ei = (const int*)  d_in[2];
    const float* W      = (const float*)d_in[3];
    const float* b      = (const float*)d_in[4];
    float*       out    = (float*)d_out;

    // R1 launch shape: 1184 blocks x 256 threads, ~7 edges per warp grid-stride.
    ncn_kernel<<<1184, 256>>>(x, nbr, tar_ei, W, b, out);
}